// round 16
// baseline (speedup 1.0000x reference)
#include <cuda_runtime.h>
#include <cuda_fp16.h>
#include <math.h>
#include <stdint.h>

#define B    4
#define N    16384
#define CIN  4
#define SD   3
#define W    256
#define L    8
#define M    32
#define H    8
#define FF   1024
#define TF   4
#define DH   32
#define TOK1 64
#define TOKF 128
#define JC2  128

__device__ float g_x[(size_t)B * N * W];
__device__ float g_w[(size_t)B * N * M];
__device__ float g_z[(size_t)L * B * M * W];
__device__ float g_wsum[L * B * M];
__device__ float g_qkv[B * M * 3 * W];
__device__ float g_o[B * M * W];
__device__ float g_zp[B * M * W];
__device__ __align__(16) __half g_w1t[(size_t)L * FF * W];   // [L][FF][W] fp16, word-permuted
__device__ __align__(16) __half g_w2t[(size_t)L * W * FF];   // [L][W][FF] fp16, word-permuted

// ---------- helpers ----------
// word permutation within groups of 8: logical (0,1,..,7) stored as (0,4,1,5,2,6,3,7)^-1
// i.e. logical word w stored at pw(w); pairs (w, w+4) land at (2w, 2w+1) within group.
__device__ __forceinline__ int pw(int w) {
    return (w & ~7) | ((w & 3) << 1) | ((w >> 2) & 1);
}
__device__ __forceinline__ void mma16(float* d, const uint32_t* a, const uint32_t* b) {
    asm volatile("mma.sync.aligned.m16n8k16.row.col.f32.f16.f16.f32 "
        "{%0,%1,%2,%3}, {%4,%5,%6,%7}, {%8,%9}, {%0,%1,%2,%3};"
        : "+f"(d[0]), "+f"(d[1]), "+f"(d[2]), "+f"(d[3])
        : "r"(a[0]), "r"(a[1]), "r"(a[2]), "r"(a[3]), "r"(b[0]), "r"(b[1]));
}

// ---------------- K0: embed ----------------
__global__ void __launch_bounds__(256) embed_kernel(
    const float* __restrict__ feat, const float* __restrict__ coords,
    const float* __restrict__ tn, const float* __restrict__ ew, const float* __restrict__ eb)
{
    __shared__ float f[16][16];
    int t0 = blockIdx.x * 16;
    int tid = threadIdx.x;
    {
        int t = tid >> 4, k = tid & 15;
        int token = t0 + t, b = token / N;
        float v = 0.f;
        if (k < CIN) v = feat[(size_t)token * CIN + k];
        else if (k < CIN + SD) v = coords[(size_t)token * SD + (k - CIN)];
        else if (k < 15) {
            int kk = k - 7, i = kk & 3;
            float ang = powf(1000.0f, -(float)i / (float)TF) * (tn[b] * 1000.0f);
            v = (kk < TF) ? sinf(ang) : cosf(ang);
        }
        f[t][k] = v;
    }
    __syncthreads();
    int c = tid;
    float wreg[15];
#pragma unroll
    for (int k = 0; k < 15; k++) wreg[k] = ew[k * W + c];
    float bias = eb[c];
#pragma unroll 4
    for (int t = 0; t < 16; t++) {
        float acc = bias;
#pragma unroll
        for (int k = 0; k < 15; k++) acc += f[t][k] * wreg[k];
        g_x[(size_t)(t0 + t) * W + c] = acc;
    }
}

// ---------------- weight transform (fp16 + transpose + word-permute) -------
__global__ void __launch_bounds__(256) w1t_kernel(const float* __restrict__ f1w)
{
    int idx = blockIdx.x * 256 + threadIdx.x;
    int l = idx / (FF * W), r = idx % (FF * W), j = r / W, c = r % W;
    int dc = pw(c >> 1) * 2 + (c & 1);
    g_w1t[((size_t)l * FF + j) * W + dc] =
        __float2half(f1w[((size_t)l * W + c) * FF + j]);
}
#define NB_W2T (L * W * FF / 256)
#define NB_Z   (L * B * M * W / 256)
__global__ void __launch_bounds__(256) w2t_zero_kernel(const float* __restrict__ f2w)
{
    int bid = blockIdx.x;
    if (bid < NB_W2T) {
        int idx = bid * 256 + threadIdx.x;
        int l = idx / (W * FF), r = idx % (W * FF), c = r / FF, j = r % FF;
        int dj = pw(j >> 1) * 2 + (j & 1);
        g_w2t[((size_t)l * W + c) * FF + dj] =
            __float2half(f2w[((size_t)l * FF + j) * W + c]);
    } else if (bid < NB_W2T + NB_Z) {
        int idx = (bid - NB_W2T) * 256 + threadIdx.x;
        g_z[idx] = 0.f;
    } else {
        for (int i = threadIdx.x; i < L * B * M; i += 256) g_wsum[i] = 0.f;
    }
}

// ---------------- K1: slice (64 tokens / block) ----------------
#define SLICE_SMEM ((TOK1 * W + TOK1 * M + TOK1) * 4)

__global__ void __launch_bounds__(256, 3) slice_kernel(
    const float* __restrict__ ln_g, const float* __restrict__ ln_b,
    const float* __restrict__ sw, const float* __restrict__ sb, int layer)
{
    extern __shared__ float ssm[];
    float* hs  = ssm;
    float* ws  = ssm + TOK1 * W;
    float* inv = ws + TOK1 * M;
    int nb = N / TOK1, b = blockIdx.x / nb, t0 = (blockIdx.x % nb) * TOK1;
    int tid = threadIdx.x, warp = tid >> 5, lane = tid & 31;
    const float* g = ln_g + layer * W;
    const float* be = ln_b + layer * W;
    float* zdst = g_z + (size_t)layer * B * M * W;
    float* wsdst = g_wsum + layer * B * M;

    for (int t = warp; t < TOK1; t += 8) {
        const float* xr = g_x + ((size_t)(b * N + t0 + t)) * W;
        float v[8]; float s = 0.f, s2 = 0.f;
#pragma unroll
        for (int i = 0; i < 8; i++) { v[i] = xr[lane + 32 * i]; s += v[i]; s2 += v[i] * v[i]; }
#pragma unroll
        for (int o = 16; o > 0; o >>= 1) {
            s += __shfl_xor_sync(0xffffffffu, s, o);
            s2 += __shfl_xor_sync(0xffffffffu, s2, o);
        }
        float mean = s * (1.0f / W), var = s2 * (1.0f / W) - mean * mean;
        float r = rsqrtf(var + 1e-5f);
#pragma unroll
        for (int i = 0; i < 8; i++) {
            int c = lane + 32 * i;
            hs[t * W + c] = (v[i] - mean) * r * g[c] + be[c];
        }
    }
    __syncthreads();

    const float* swl = sw + (size_t)layer * W * M;
#pragma unroll
    for (int r = 0; r < 2; r++) {
        int idx = tid + 256 * r;
        int t = idx >> 3, m4 = (idx & 7) << 2;
        float4 acc = *(const float4*)&sb[layer * M + m4];
#pragma unroll 4
        for (int c4 = 0; c4 < W; c4 += 4) {
            float4 hv = *(const float4*)&hs[t * W + c4];
            float4 s0 = *(const float4*)&swl[(c4 + 0) * M + m4];
            float4 s1 = *(const float4*)&swl[(c4 + 1) * M + m4];
            float4 s2 = *(const float4*)&swl[(c4 + 2) * M + m4];
            float4 s3 = *(const float4*)&swl[(c4 + 3) * M + m4];
            acc.x += hv.x * s0.x + hv.y * s1.x + hv.z * s2.x + hv.w * s3.x;
            acc.y += hv.x * s0.y + hv.y * s1.y + hv.z * s2.y + hv.w * s3.y;
            acc.z += hv.x * s0.z + hv.y * s1.z + hv.z * s2.z + hv.w * s3.z;
            acc.w += hv.x * s0.w + hv.y * s1.w + hv.z * s2.w + hv.w * s3.w;
        }
        *(float4*)&ws[t * M + m4] = acc;
    }
    __syncthreads();

    if (tid < TOK1) {
        float mx = -1e30f;
#pragma unroll
        for (int m = 0; m < M; m++) mx = fmaxf(mx, ws[tid * M + m]);
        float sum = 0.f;
#pragma unroll
        for (int m = 0; m < M; m++) { float e = expf(ws[tid * M + m] - mx); ws[tid * M + m] = e; sum += e; }
        inv[tid] = 1.0f / sum;
    }
    __syncthreads();

#pragma unroll
    for (int r = 0; r < 2; r++) {
        int idx = tid + 256 * r;
        int t = idx >> 3, m4 = (idx & 7) << 2;
        float iv = inv[t];
        float4 v = *(const float4*)&ws[t * M + m4];
        v.x *= iv; v.y *= iv; v.z *= iv; v.w *= iv;
        *(float4*)&ws[t * M + m4] = v;
        *(float4*)&g_w[((size_t)(b * N + t0 + t)) * M + m4] = v;
    }
    __syncthreads();

    if (tid < M) {
        float s = 0.f;
#pragma unroll
        for (int t = 0; t < TOK1; t++) s += ws[t * M + tid];
        atomicAdd(&wsdst[b * M + tid], s);
    }

    float zacc[M];
#pragma unroll
    for (int m = 0; m < M; m++) zacc[m] = 0.f;
    for (int t = 0; t < TOK1; t++) {
        float hv = hs[t * W + tid];
#pragma unroll
        for (int mq = 0; mq < 8; mq++) {
            float4 wv = *(const float4*)&ws[t * M + (mq << 2)];
            zacc[(mq << 2) + 0] += wv.x * hv;
            zacc[(mq << 2) + 1] += wv.y * hv;
            zacc[(mq << 2) + 2] += wv.z * hv;
            zacc[(mq << 2) + 3] += wv.w * hv;
        }
    }
#pragma unroll
    for (int m = 0; m < M; m++) atomicAdd(&zdst[(b * M + m) * W + tid], zacc[m]);
}

// ---------------- K2a/b/c ----------------
__global__ void __launch_bounds__(768) qkv_kernel(
    const float* __restrict__ qkvw, const float* __restrict__ qkvb, int layer)
{
    int b = blockIdx.x / M, m = blockIdx.x % M;
    __shared__ float zs[W];
    int tid = threadIdx.x;
    if (tid < W) {
        float wsv = fmaxf(g_wsum[layer * B * M + b * M + m], 1e-8f);
        zs[tid] = g_z[(size_t)layer * B * M * W + (size_t)(b * M + m) * W + tid] / wsv;
    }
    __syncthreads();
    const float* wq = qkvw + (size_t)layer * W * 3 * W;
    float acc = qkvb[layer * 3 * W + tid];
#pragma unroll 8
    for (int c = 0; c < W; c++) acc += zs[c] * wq[(size_t)c * (3 * W) + tid];
    g_qkv[(size_t)(b * M + m) * (3 * W) + tid] = acc;
}

__global__ void __launch_bounds__(256) attn_kernel()
{
    int b = blockIdx.x / H, h = blockIdx.x % H;
    __shared__ float q[M][DH], k[M][DH], v[M][DH], a[M][M];
    int tid = threadIdx.x;
    for (int i = tid; i < M * DH; i += 256) {
        int m = i / DH, d = i % DH;
        const float* base = g_qkv + (size_t)(b * M + m) * (3 * W);
        q[m][d] = base[h * DH + d];
        k[m][d] = base[W + h * DH + d];
        v[m][d] = base[2 * W + h * DH + d];
    }
    __syncthreads();
    const float scale = 0.17677669529663687f;
    for (int i = tid; i < M * M; i += 256) {
        int m = i / M, n2 = i % M;
        float acc = 0.f;
#pragma unroll
        for (int d = 0; d < DH; d++) acc += q[m][d] * k[n2][d];
        a[m][n2] = acc * scale;
    }
    __syncthreads();
    if (tid < M) {
        float mx = -1e30f;
#pragma unroll
        for (int n2 = 0; n2 < M; n2++) mx = fmaxf(mx, a[tid][n2]);
        float s = 0.f;
#pragma unroll
        for (int n2 = 0; n2 < M; n2++) { float e = expf(a[tid][n2] - mx); a[tid][n2] = e; s += e; }
        float is = 1.0f / s;
#pragma unroll
        for (int n2 = 0; n2 < M; n2++) a[tid][n2] *= is;
    }
    __syncthreads();
    for (int i = tid; i < M * DH; i += 256) {
        int m = i / DH, d = i % DH;
        float acc = 0.f;
#pragma unroll
        for (int n2 = 0; n2 < M; n2++) acc += a[m][n2] * v[n2][d];
        g_o[(size_t)(b * M + m) * W + h * DH + d] = acc;
    }
}
__global__ void __launch_bounds__(256) zp_kernel(
    const float* __restrict__ ow, const float* __restrict__ ob, int layer)
{
    int b = blockIdx.x / M, m = blockIdx.x % M;
    __shared__ float os[W];
    os[threadIdx.x] = g_o[(size_t)(b * M + m) * W + threadIdx.x];
    __syncthreads();
    const float* wl = ow + (size_t)layer * W * W;
    float acc = ob[layer * W + threadIdx.x];
#pragma unroll 8
    for (int k2 = 0; k2 < W; k2++) acc += os[k2] * wl[(size_t)k2 * W + threadIdx.x];
    g_zp[(size_t)(b * M + m) * W + threadIdx.x] = acc;
}

// ---------------- K3: FFN fp16 m16n8k16, permuted words + LDS.64 ----------
#define WO_G 16384
#define WO_B 24576
#define SM_FFN_BYTES (40960 * 4)

__global__ void __launch_bounds__(512, 1) ffn_mma_kernel(
    const float* __restrict__ ln2g, const float* __restrict__ ln2b,
    const float* __restrict__ f1b, const float* __restrict__ f2b, int layer)
{
    extern __shared__ uint32_t usm[];
    uint32_t* u_h2 = usm;
    uint32_t* u_g  = usm + WO_G;
    uint32_t* u_b  = usm + WO_B;
    __half* h_h2 = (__half*)u_h2;
    int tid = threadIdx.x;
    int warp = tid >> 5, lane = tid & 31, g = lane >> 2, tig = lane & 3;
    int nb = N / TOKF, b = blockIdx.x / nb, t0 = (blockIdx.x % nb) * TOKF;
    size_t xbase = ((size_t)(b * N) + t0) * W;

    // ---- prologue: x_mid = x + w@zp (write h2 word-permuted + row-XOR) ----
    int c = tid & 255, half_ = tid >> 8;
    float zpc[M];
#pragma unroll
    for (int m = 0; m < M; m++) zpc[m] = g_zp[(size_t)(b * M + m) * W + c];
    {
        float* s_w = (float*)u_g;
        for (int i = tid; i < TOKF * M; i += 512)
            s_w[i] = g_w[((size_t)(b * N) + t0 + i / M) * M + (i % M)];
        __syncthreads();
        int wcs = pw(c >> 1), hi = c & 1;
        for (int t = half_ * 64; t < half_ * 64 + 64; t++) {
            float acc = g_x[xbase + (size_t)t * W + c];
#pragma unroll
            for (int m = 0; m < M; m++) acc += s_w[t * M + m] * zpc[m];
            g_x[xbase + (size_t)t * W + c] = acc;
            h_h2[(t * 128 + (wcs ^ ((t & 7) << 2))) * 2 + hi] = __float2half(acc);
        }
    }
    __syncthreads();

    // ---- LN2 in place on fp16 h2 ----
    {
        const float* g2 = ln2g + layer * W;
        const float* b2 = ln2b + layer * W;
        for (int rr = 0; rr < 8; rr++) {
            int r = warp * 8 + rr;
            if (r >= TOKF) break;
            float v[8]; float s = 0.f, s2 = 0.f;
#pragma unroll
            for (int i = 0; i < 8; i++) {
                int ci = lane + 32 * i;
                v[i] = __half2float(h_h2[(r * 128 + (pw(ci >> 1) ^ ((r & 7) << 2))) * 2 + (ci & 1)]);
                s += v[i]; s2 += v[i] * v[i];
            }
#pragma unroll
            for (int o = 16; o > 0; o >>= 1) {
                s += __shfl_xor_sync(0xffffffffu, s, o);
                s2 += __shfl_xor_sync(0xffffffffu, s2, o);
            }
            float mean = s * (1.0f / W), var = s2 * (1.0f / W) - mean * mean;
            float rs = rsqrtf(var + 1e-5f);
#pragma unroll
            for (int i = 0; i < 8; i++) {
                int ci = lane + 32 * i;
                h_h2[(r * 128 + (pw(ci >> 1) ^ ((r & 7) << 2))) * 2 + (ci & 1)] =
                    __float2half((v[i] - mean) * rs * g2[ci] + b2[ci]);
            }
        }
    }

    const __half* w1l = g_w1t + (size_t)layer * FF * W;
    const __half* w2l = g_w2t + (size_t)layer * W * FF;
    const float* b1l = f1b + layer * FF;

    int wm = warp >> 2, wn = warp & 3;
    float d2[2][8][4];
#pragma unroll
    for (int mt = 0; mt < 2; mt++)
#pragma unroll
        for (int nt = 0; nt < 8; nt++)
#pragma unroll
            for (int q = 0; q < 4; q++) d2[mt][nt][q] = 0.f;

    for (int chunk = 0; chunk < 8; chunk++) {
        int j0 = chunk * JC2;

        __syncthreads();
        // stage B1 (gmem already permuted -> raw copy with row-XOR)
#pragma unroll
        for (int it = 0; it < 8; it++) {
            int idx = it * 512 + tid;
            int jl = idx >> 5, wc4 = (idx & 31) << 2;
            uint4 v = *(const uint4*)&w1l[(size_t)(j0 + jl) * W + wc4 * 2];
            *(uint4*)&u_b[jl * 128 + (wc4 ^ ((jl & 7) << 2))] = v;
        }
        __syncthreads();

        // ===== GEMM1: D1[128x128] = h2 @ B1, K=256 =====
        float d1[2][4][4];
#pragma unroll
        for (int mt = 0; mt < 2; mt++)
#pragma unroll
            for (int nt = 0; nt < 4; nt++)
#pragma unroll
                for (int q = 0; q < 4; q++) d1[mt][nt][q] = 0.f;

#pragma unroll 4
        for (int ks = 0; ks < 16; ks++) {
            int kwb = ks * 8;
            uint32_t af[2][4];
#pragma unroll
            for (int mt = 0; mt < 2; mt++) {
                int r0 = wm * 32 + mt * 16 + g;
                uint2 a0 = *(const uint2*)&u_h2[r0 * 128 + ((kwb + 2 * tig) ^ ((r0 & 7) << 2))];
                int r1 = r0 + 8;
                uint2 a1 = *(const uint2*)&u_h2[r1 * 128 + ((kwb + 2 * tig) ^ ((r1 & 7) << 2))];
                af[mt][0] = a0.x; af[mt][2] = a0.y;
                af[mt][1] = a1.x; af[mt][3] = a1.y;
            }
#pragma unroll
            for (int nt = 0; nt < 4; nt++) {
                int jl = wn * 32 + nt * 8 + g;
                uint2 bv = *(const uint2*)&u_b[jl * 128 + ((kwb + 2 * tig) ^ ((jl & 7) << 2))];
                uint32_t bf[2] = { bv.x, bv.y };
                mma16(d1[0][nt], af[0], bf);
                mma16(d1[1][nt], af[1], bf);
            }
        }
        __syncthreads();

        // ---- gelu -> G (word-permuted) ; stage B2 ----
#pragma unroll
        for (int mt = 0; mt < 2; mt++) {
#pragma unroll
            for (int nt = 0; nt < 4; nt++) {
                int r0 = wm * 32 + mt * 16 + g;
                int jc = wn * 32 + nt * 8 + 2 * tig;
                int wc = wn * 16 + nt * 4 + tig;
                int wcs = pw(wc);
                float x0 = d1[mt][nt][0] + b1l[j0 + jc];
                float x1 = d1[mt][nt][1] + b1l[j0 + jc + 1];
                float x2 = d1[mt][nt][2] + b1l[j0 + jc];
                float x3 = d1[mt][nt][3] + b1l[j0 + jc + 1];
                float g0 = 0.5f * x0 * (1.0f + erff(x0 * 0.7071067811865476f));
                float g1 = 0.5f * x1 * (1.0f + erff(x1 * 0.7071067811865476f));
                float g2v = 0.5f * x2 * (1.0f + erff(x2 * 0.7071067811865476f));
                float g3 = 0.5f * x3 * (1.0f + erff(x3 * 0.7071067811865476f));
                __half2 p0 = __floats2half2_rn(g0, g1);
                __half2 p1 = __floats2half2_rn(g2v, g3);
                u_g[r0 * 64 + (wcs ^ ((r0 & 7) << 2))] = *(uint32_t*)&p0;
                int r1 = r0 + 8;
                u_g[r1 * 64 + (wcs ^ ((r1 & 7) << 2))] = *(uint32_t*)&p1;
            }
        }
#pragma unroll
        for (int it = 0; it < 8; it++) {
            int idx = it * 512 + tid;
            int cc = idx >> 4, wc4 = (idx & 15) << 2;
            uint4 v = *(const uint4*)&w2l[(size_t)cc * FF + j0 + wc4 * 2];
            *(uint4*)&u_b[cc * 64 + (wc4 ^ ((cc & 7) << 2))] = v;
        }
        __syncthreads();

        // ===== GEMM2 partial: D2[128x256] += G @ B2, K=128 =====
#pragma unroll 2
        for (int ks = 0; ks < 8; ks++) {
            int kwb = ks * 8;
            uint32_t af[2][4];
#pragma unroll
            for (int mt = 0; mt < 2; mt++) {
                int r0 = wm * 32 + mt * 16 + g;
                uint2 a0 = *(const uint2*)&u_g[r0 * 64 + ((kwb + 2 * tig) ^ ((r0 & 7) << 2))];
                int r1 = r0 + 8;
                uint2 a1 = *(const uint2*)&u_g[r1 * 64 + ((kwb + 2 * tig) ^ ((r1 & 7) << 2))];
                af[mt][0] = a0.x; af[mt][2] = a0.y;
                af[mt][1] = a1.x; af[mt][3] = a1.y;
            }
#pragma unroll
            for (int nt = 0; nt < 8; nt++) {
                int cc = wn * 64 + nt * 8 + g;
                uint2 bv = *(const uint2*)&u_b[cc * 64 + ((kwb + 2 * tig) ^ ((cc & 7) << 2))];
                uint32_t bf[2] = { bv.x, bv.y };
                mma16(d2[0][nt], af[0], bf);
                mma16(d2[1][nt], af[1], bf);
            }
        }
    }

    // ---- epilogue: x = x_mid + D2 + b2 ----
    const float* b2l = f2b + layer * W;
#pragma unroll
    for (int mt = 0; mt < 2; mt++) {
#pragma unroll
        for (int nt = 0; nt < 8; nt++) {
            int col = wn * 64 + nt * 8 + 2 * tig;
            int ra = wm * 32 + mt * 16 + g;
            float2 xm = *(const float2*)&g_x[xbase + (size_t)ra * W + col];
            float2 o;
            o.x = xm.x + d2[mt][nt][0] + b2l[col];
            o.y = xm.y + d2[mt][nt][1] + b2l[col + 1];
            *(float2*)&g_x[xbase + (size_t)ra * W + col] = o;
            int rb = ra + 8;
            float2 xm2 = *(const float2*)&g_x[xbase + (size_t)rb * W + col];
            o.x = xm2.x + d2[mt][nt][2] + b2l[col];
            o.y = xm2.y + d2[mt][nt][3] + b2l[col + 1];
            *(float2*)&g_x[xbase + (size_t)rb * W + col] = o;
        }
    }
}

// ---------------- K5: final projection ----------------
__global__ void __launch_bounds__(256) proj_kernel(
    const float* __restrict__ pw_, const float* __restrict__ pb, float* __restrict__ out)
{
    __shared__ float xs[16][W];
    size_t t0 = (size_t)blockIdx.x * 16;
    for (int i = threadIdx.x; i < 16 * W; i += 256)
        xs[i >> 8][i & 255] = g_x[t0 * W + i];
    __syncthreads();
    if (threadIdx.x < 64) {
        int t = threadIdx.x >> 2, o = threadIdx.x & 3;
        float acc = pb[o];
#pragma unroll 8
        for (int c = 0; c < W; c++) acc += xs[t][c] * pw_[c * CIN + o];
        out[(t0 + t) * CIN + o] = acc;
    }
}

// ---------------- launch ----------------
extern "C" void kernel_launch(void* const* d_in, const int* in_sizes, int n_in,
                              void* d_out, int out_size)
{
    const float* feat = (const float*)d_in[0];
    const float* coords = (const float*)d_in[1];
    const float* tn   = (const float*)d_in[2];
    const float* ew   = (const float*)d_in[3];
    const float* eb   = (const float*)d_in[4];
    const float* ln1g = (const float*)d_in[5];
    const float* ln1b = (const float*)d_in[6];
    const float* sw   = (const float*)d_in[7];
    const float* sb   = (const float*)d_in[8];
    const float* qkvw = (const float*)d_in[9];
    const float* qkvb = (const float*)d_in[10];
    const float* outw = (const float*)d_in[11];
    const float* outb = (const float*)d_in[12];
    const float* ln2g = (const float*)d_in[13];
    const float* ln2b = (const float*)d_in[14];
    const float* f1w  = (const float*)d_in[15];
    const float* f1b  = (const float*)d_in[16];
    const float* f2w  = (const float*)d_in[17];
    const float* f2b  = (const float*)d_in[18];
    const float* pwp  = (const float*)d_in[19];
    const float* pb   = (const float*)d_in[20];

    static int attr_set = 0;
    if (!attr_set) {
        cudaFuncSetAttribute(ffn_mma_kernel, cudaFuncAttributeMaxDynamicSharedMemorySize, SM_FFN_BYTES);
        cudaFuncSetAttribute(slice_kernel, cudaFuncAttributeMaxDynamicSharedMemorySize, SLICE_SMEM);
        attr_set = 1;
    }

    embed_kernel<<<B * N / 16, 256>>>(feat, coords, tn, ew, eb);
    w1t_kernel<<<L * FF * W / 256, 256>>>(f1w);
    w2t_zero_kernel<<<NB_W2T + NB_Z + 1, 256>>>(f2w);

    for (int l = 0; l < L; l++) {
        slice_kernel<<<B * (N / TOK1), 256, SLICE_SMEM>>>(ln1g, ln1b, sw, sb, l);
        qkv_kernel<<<B * M, 768>>>(qkvw, qkvb, l);
        attn_kernel<<<B * H, 256>>>();
        zp_kernel<<<B * M, 256>>>(outw, outb, l);
        ffn_mma_kernel<<<B * (N / TOKF), 512, SM_FFN_BYTES>>>(ln2g, ln2b, f1b, f2b, l);
    }

    proj_kernel<<<(B * N) / 16, 256>>>(pwp, pb, (float*)d_out);
}

// round 17
// speedup vs baseline: 1.1164x; 1.1164x over previous
#include <cuda_runtime.h>
#include <cuda_fp16.h>
#include <math.h>
#include <stdint.h>

#define B    4
#define N    16384
#define CIN  4
#define SD   3
#define W    256
#define L    8
#define M    32
#define H    8
#define FF   1024
#define TF   4
#define DH   32
#define TOK1 64
#define TOKF 128
#define JC2  128

__device__ float g_x[(size_t)B * N * W];
__device__ float g_w[(size_t)B * N * M];
__device__ float g_z[(size_t)L * B * M * W];
__device__ float g_wsum[L * B * M];
__device__ float g_qkv[B * M * 3 * W];
__device__ float g_o[B * M * W];
__device__ float g_zp[B * M * W];
__device__ __align__(16) __half g_w1t[(size_t)L * FF * W];   // [L][FF][W] fp16
__device__ __align__(16) __half g_w2t[(size_t)L * W * FF];   // [L][W][FF] fp16

// ---------- helpers ----------
__device__ __forceinline__ void mma16(float* d, const uint32_t* a, const uint32_t* b) {
    asm volatile("mma.sync.aligned.m16n8k16.row.col.f32.f16.f16.f32 "
        "{%0,%1,%2,%3}, {%4,%5,%6,%7}, {%8,%9}, {%0,%1,%2,%3};"
        : "+f"(d[0]), "+f"(d[1]), "+f"(d[2]), "+f"(d[3])
        : "r"(a[0]), "r"(a[1]), "r"(a[2]), "r"(a[3]), "r"(b[0]), "r"(b[1]));
}
__device__ __forceinline__ void ldsm4(uint32_t* r, uint32_t saddr) {
    asm volatile("ldmatrix.sync.aligned.m8n8.x4.shared.b16 {%0,%1,%2,%3}, [%4];"
        : "=r"(r[0]), "=r"(r[1]), "=r"(r[2]), "=r"(r[3]) : "r"(saddr));
}

// ---------------- K0: embed ----------------
__global__ void __launch_bounds__(256) embed_kernel(
    const float* __restrict__ feat, const float* __restrict__ coords,
    const float* __restrict__ tn, const float* __restrict__ ew, const float* __restrict__ eb)
{
    __shared__ float f[16][16];
    int t0 = blockIdx.x * 16;
    int tid = threadIdx.x;
    {
        int t = tid >> 4, k = tid & 15;
        int token = t0 + t, b = token / N;
        float v = 0.f;
        if (k < CIN) v = feat[(size_t)token * CIN + k];
        else if (k < CIN + SD) v = coords[(size_t)token * SD + (k - CIN)];
        else if (k < 15) {
            int kk = k - 7, i = kk & 3;
            float ang = powf(1000.0f, -(float)i / (float)TF) * (tn[b] * 1000.0f);
            v = (kk < TF) ? sinf(ang) : cosf(ang);
        }
        f[t][k] = v;
    }
    __syncthreads();
    int c = tid;
    float wreg[15];
#pragma unroll
    for (int k = 0; k < 15; k++) wreg[k] = ew[k * W + c];
    float bias = eb[c];
#pragma unroll 4
    for (int t = 0; t < 16; t++) {
        float acc = bias;
#pragma unroll
        for (int k = 0; k < 15; k++) acc += f[t][k] * wreg[k];
        g_x[(size_t)(t0 + t) * W + c] = acc;
    }
}

// ---------------- weight transform + zero ----------------
__global__ void __launch_bounds__(256) w1t_kernel(const float* __restrict__ f1w)
{
    int idx = blockIdx.x * 256 + threadIdx.x;
    int l = idx / (FF * W), r = idx % (FF * W), j = r / W, c = r % W;
    g_w1t[((size_t)l * FF + j) * W + c] =
        __float2half(f1w[((size_t)l * W + c) * FF + j]);
}
#define NB_W2T (L * W * FF / 256)
#define NB_Z   (L * B * M * W / 256)
__global__ void __launch_bounds__(256) w2t_zero_kernel(const float* __restrict__ f2w)
{
    int bid = blockIdx.x;
    if (bid < NB_W2T) {
        int idx = bid * 256 + threadIdx.x;
        int l = idx / (W * FF), r = idx % (W * FF), c = r / FF, j = r % FF;
        g_w2t[((size_t)l * W + c) * FF + j] =
            __float2half(f2w[((size_t)l * FF + j) * W + c]);
    } else if (bid < NB_W2T + NB_Z) {
        int idx = (bid - NB_W2T) * 256 + threadIdx.x;
        g_z[idx] = 0.f;
    } else {
        for (int i = threadIdx.x; i < L * B * M; i += 256) g_wsum[i] = 0.f;
    }
}

// ---------------- K1: slice (64 tokens / block) ----------------
#define SLICE_SMEM ((TOK1 * W + TOK1 * M + TOK1) * 4)

__global__ void __launch_bounds__(256, 3) slice_kernel(
    const float* __restrict__ ln_g, const float* __restrict__ ln_b,
    const float* __restrict__ sw, const float* __restrict__ sb, int layer)
{
    extern __shared__ float ssm[];
    float* hs  = ssm;
    float* ws  = ssm + TOK1 * W;
    float* inv = ws + TOK1 * M;
    int nb = N / TOK1, b = blockIdx.x / nb, t0 = (blockIdx.x % nb) * TOK1;
    int tid = threadIdx.x, warp = tid >> 5, lane = tid & 31;
    const float* g = ln_g + layer * W;
    const float* be = ln_b + layer * W;
    float* zdst = g_z + (size_t)layer * B * M * W;
    float* wsdst = g_wsum + layer * B * M;

    for (int t = warp; t < TOK1; t += 8) {
        const float* xr = g_x + ((size_t)(b * N + t0 + t)) * W;
        float v[8]; float s = 0.f, s2 = 0.f;
#pragma unroll
        for (int i = 0; i < 8; i++) { v[i] = xr[lane + 32 * i]; s += v[i]; s2 += v[i] * v[i]; }
#pragma unroll
        for (int o = 16; o > 0; o >>= 1) {
            s += __shfl_xor_sync(0xffffffffu, s, o);
            s2 += __shfl_xor_sync(0xffffffffu, s2, o);
        }
        float mean = s * (1.0f / W), var = s2 * (1.0f / W) - mean * mean;
        float r = rsqrtf(var + 1e-5f);
#pragma unroll
        for (int i = 0; i < 8; i++) {
            int c = lane + 32 * i;
            hs[t * W + c] = (v[i] - mean) * r * g[c] + be[c];
        }
    }
    __syncthreads();

    const float* swl = sw + (size_t)layer * W * M;
#pragma unroll
    for (int r = 0; r < 2; r++) {
        int idx = tid + 256 * r;
        int t = idx >> 3, m4 = (idx & 7) << 2;
        float4 acc = *(const float4*)&sb[layer * M + m4];
#pragma unroll 4
        for (int c4 = 0; c4 < W; c4 += 4) {
            float4 hv = *(const float4*)&hs[t * W + c4];
            float4 s0 = *(const float4*)&swl[(c4 + 0) * M + m4];
            float4 s1 = *(const float4*)&swl[(c4 + 1) * M + m4];
            float4 s2 = *(const float4*)&swl[(c4 + 2) * M + m4];
            float4 s3 = *(const float4*)&swl[(c4 + 3) * M + m4];
            acc.x += hv.x * s0.x + hv.y * s1.x + hv.z * s2.x + hv.w * s3.x;
            acc.y += hv.x * s0.y + hv.y * s1.y + hv.z * s2.y + hv.w * s3.y;
            acc.z += hv.x * s0.z + hv.y * s1.z + hv.z * s2.z + hv.w * s3.z;
            acc.w += hv.x * s0.w + hv.y * s1.w + hv.z * s2.w + hv.w * s3.w;
        }
        *(float4*)&ws[t * M + m4] = acc;
    }
    __syncthreads();

    if (tid < TOK1) {
        float mx = -1e30f;
#pragma unroll
        for (int m = 0; m < M; m++) mx = fmaxf(mx, ws[tid * M + m]);
        float sum = 0.f;
#pragma unroll
        for (int m = 0; m < M; m++) { float e = expf(ws[tid * M + m] - mx); ws[tid * M + m] = e; sum += e; }
        inv[tid] = 1.0f / sum;
    }
    __syncthreads();

#pragma unroll
    for (int r = 0; r < 2; r++) {
        int idx = tid + 256 * r;
        int t = idx >> 3, m4 = (idx & 7) << 2;
        float iv = inv[t];
        float4 v = *(const float4*)&ws[t * M + m4];
        v.x *= iv; v.y *= iv; v.z *= iv; v.w *= iv;
        *(float4*)&ws[t * M + m4] = v;
        *(float4*)&g_w[((size_t)(b * N + t0 + t)) * M + m4] = v;
    }
    __syncthreads();

    if (tid < M) {
        float s = 0.f;
#pragma unroll
        for (int t = 0; t < TOK1; t++) s += ws[t * M + tid];
        atomicAdd(&wsdst[b * M + tid], s);
    }

    float zacc[M];
#pragma unroll
    for (int m = 0; m < M; m++) zacc[m] = 0.f;
    for (int t = 0; t < TOK1; t++) {
        float hv = hs[t * W + tid];
#pragma unroll
        for (int mq = 0; mq < 8; mq++) {
            float4 wv = *(const float4*)&ws[t * M + (mq << 2)];
            zacc[(mq << 2) + 0] += wv.x * hv;
            zacc[(mq << 2) + 1] += wv.y * hv;
            zacc[(mq << 2) + 2] += wv.z * hv;
            zacc[(mq << 2) + 3] += wv.w * hv;
        }
    }
#pragma unroll
    for (int m = 0; m < M; m++) atomicAdd(&zdst[(b * M + m) * W + tid], zacc[m]);
}

// ---------------- K2a/b/c ----------------
__global__ void __launch_bounds__(768) qkv_kernel(
    const float* __restrict__ qkvw, const float* __restrict__ qkvb, int layer)
{
    int b = blockIdx.x / M, m = blockIdx.x % M;
    __shared__ float zs[W];
    int tid = threadIdx.x;
    if (tid < W) {
        float wsv = fmaxf(g_wsum[layer * B * M + b * M + m], 1e-8f);
        zs[tid] = g_z[(size_t)layer * B * M * W + (size_t)(b * M + m) * W + tid] / wsv;
    }
    __syncthreads();
    const float* wq = qkvw + (size_t)layer * W * 3 * W;
    float acc = qkvb[layer * 3 * W + tid];
#pragma unroll 8
    for (int c = 0; c < W; c++) acc += zs[c] * wq[(size_t)c * (3 * W) + tid];
    g_qkv[(size_t)(b * M + m) * (3 * W) + tid] = acc;
}

__global__ void __launch_bounds__(256) attn_kernel()
{
    int b = blockIdx.x / H, h = blockIdx.x % H;
    __shared__ float q[M][DH], k[M][DH], v[M][DH], a[M][M];
    int tid = threadIdx.x;
    for (int i = tid; i < M * DH; i += 256) {
        int m = i / DH, d = i % DH;
        const float* base = g_qkv + (size_t)(b * M + m) * (3 * W);
        q[m][d] = base[h * DH + d];
        k[m][d] = base[W + h * DH + d];
        v[m][d] = base[2 * W + h * DH + d];
    }
    __syncthreads();
    const float scale = 0.17677669529663687f;
    for (int i = tid; i < M * M; i += 256) {
        int m = i / M, n2 = i % M;
        float acc = 0.f;
#pragma unroll
        for (int d = 0; d < DH; d++) acc += q[m][d] * k[n2][d];
        a[m][n2] = acc * scale;
    }
    __syncthreads();
    if (tid < M) {
        float mx = -1e30f;
#pragma unroll
        for (int n2 = 0; n2 < M; n2++) mx = fmaxf(mx, a[tid][n2]);
        float s = 0.f;
#pragma unroll
        for (int n2 = 0; n2 < M; n2++) { float e = expf(a[tid][n2] - mx); a[tid][n2] = e; s += e; }
        float is = 1.0f / s;
#pragma unroll
        for (int n2 = 0; n2 < M; n2++) a[tid][n2] *= is;
    }
    __syncthreads();
    for (int i = tid; i < M * DH; i += 256) {
        int m = i / DH, d = i % DH;
        float acc = 0.f;
#pragma unroll
        for (int n2 = 0; n2 < M; n2++) acc += a[m][n2] * v[n2][d];
        g_o[(size_t)(b * M + m) * W + h * DH + d] = acc;
    }
}
__global__ void __launch_bounds__(256) zp_kernel(
    const float* __restrict__ ow, const float* __restrict__ ob, int layer)
{
    int b = blockIdx.x / M, m = blockIdx.x % M;
    __shared__ float os[W];
    os[threadIdx.x] = g_o[(size_t)(b * M + m) * W + threadIdx.x];
    __syncthreads();
    const float* wl = ow + (size_t)layer * W * W;
    float acc = ob[layer * W + threadIdx.x];
#pragma unroll 8
    for (int k2 = 0; k2 < W; k2++) acc += os[k2] * wl[(size_t)k2 * W + threadIdx.x];
    g_zp[(size_t)(b * M + m) * W + threadIdx.x] = acc;
}

// ---------------- K3: FFN fp16 m16n8k16, ldmatrix fragment loads ----------
#define WO_G 16384
#define WO_B 24576
#define SM_FFN_BYTES (40960 * 4)

__global__ void __launch_bounds__(512, 1) ffn_mma_kernel(
    const float* __restrict__ ln2g, const float* __restrict__ ln2b,
    const float* __restrict__ f1b, const float* __restrict__ f2b, int layer)
{
    extern __shared__ uint32_t usm[];
    uint32_t* u_h2 = usm;
    uint32_t* u_g  = usm + WO_G;
    uint32_t* u_b  = usm + WO_B;
    __half* h_h2 = (__half*)u_h2;
    int tid = threadIdx.x;
    int warp = tid >> 5, lane = tid & 31, g = lane >> 2, tig = lane & 3;
    int nb = N / TOKF, b = blockIdx.x / nb, t0 = (blockIdx.x % nb) * TOKF;
    size_t xbase = ((size_t)(b * N) + t0) * W;
    uint32_t sb32 = (uint32_t)__cvta_generic_to_shared(usm);

    // ---- prologue: x_mid = x + w@zp ----
    int c = tid & 255, half_ = tid >> 8;
    float zpc[M];
#pragma unroll
    for (int m = 0; m < M; m++) zpc[m] = g_zp[(size_t)(b * M + m) * W + c];
    {
        float* s_w = (float*)u_g;
        for (int i = tid; i < TOKF * M; i += 512)
            s_w[i] = g_w[((size_t)(b * N) + t0 + i / M) * M + (i % M)];
        __syncthreads();
        int wcol = c >> 1, hi = c & 1;
        for (int t = half_ * 64; t < half_ * 64 + 64; t++) {
            float acc = g_x[xbase + (size_t)t * W + c];
#pragma unroll
            for (int m = 0; m < M; m++) acc += s_w[t * M + m] * zpc[m];
            g_x[xbase + (size_t)t * W + c] = acc;
            h_h2[(t * 128 + (wcol ^ ((t & 7) << 2))) * 2 + hi] = __float2half(acc);
        }
    }
    __syncthreads();

    // ---- LN2 in place on fp16 h2 ----
    {
        const float* g2 = ln2g + layer * W;
        const float* b2 = ln2b + layer * W;
        for (int rr = 0; rr < 8; rr++) {
            int r = warp * 8 + rr;
            if (r >= TOKF) break;
            float v[8]; float s = 0.f, s2 = 0.f;
#pragma unroll
            for (int i = 0; i < 8; i++) {
                int ci = lane + 32 * i;
                v[i] = __half2float(h_h2[(r * 128 + ((ci >> 1) ^ ((r & 7) << 2))) * 2 + (ci & 1)]);
                s += v[i]; s2 += v[i] * v[i];
            }
#pragma unroll
            for (int o = 16; o > 0; o >>= 1) {
                s += __shfl_xor_sync(0xffffffffu, s, o);
                s2 += __shfl_xor_sync(0xffffffffu, s2, o);
            }
            float mean = s * (1.0f / W), var = s2 * (1.0f / W) - mean * mean;
            float rs = rsqrtf(var + 1e-5f);
#pragma unroll
            for (int i = 0; i < 8; i++) {
                int ci = lane + 32 * i;
                h_h2[(r * 128 + ((ci >> 1) ^ ((r & 7) << 2))) * 2 + (ci & 1)] =
                    __float2half((v[i] - mean) * rs * g2[ci] + b2[ci]);
            }
        }
    }

    const __half* w1l = g_w1t + (size_t)layer * FF * W;
    const __half* w2l = g_w2t + (size_t)layer * W * FF;
    const float* b1l = f1b + layer * FF;

    int wm = warp >> 2, wn = warp & 3;

    // ---- ldmatrix per-lane address precompute ----
    int lq = lane >> 3, lr = lane & 7;
    int rowT = lr + ((lq & 1) << 3);              // 0..15 within A tile
    int koffA = (lq >> 1) << 2;                   // words 0 or 4
    int rowA0 = wm * 32 + rowT, rowA1 = rowA0 + 16;
    int xA0 = (rowA0 & 7) << 2, xA1 = (rowA1 & 7) << 2;
    uint32_t bA0h = sb32 + rowA0 * 128 * 4;       // h2 bases
    uint32_t bA1h = sb32 + rowA1 * 128 * 4;
    uint32_t bA0g = sb32 + WO_G * 4 + rowA0 * 64 * 4;   // G bases
    uint32_t bA1g = sb32 + WO_G * 4 + rowA1 * 64 * 4;
    int ntsel = lq >> 1, koffB = (lq & 1) << 2;
    // GEMM1 B: p=0,1 -> n-tiles (2p+ntsel)
    int jlB0 = wn * 32 + (0 + ntsel) * 8 + lr;
    int jlB1 = wn * 32 + (2 + ntsel) * 8 + lr;
    uint32_t bB0 = sb32 + WO_B * 4 + jlB0 * 128 * 4; int xB0 = (jlB0 & 7) << 2;
    uint32_t bB1 = sb32 + WO_B * 4 + jlB1 * 128 * 4; int xB1 = (jlB1 & 7) << 2;
    // GEMM2 B: p=0..3 -> n-tiles (2p+ntsel), row stride 64 words
    int ccB[4]; uint32_t bC[4]; int xC[4];
#pragma unroll
    for (int p = 0; p < 4; p++) {
        ccB[p] = wn * 64 + (2 * p + ntsel) * 8 + lr;
        bC[p] = sb32 + WO_B * 4 + ccB[p] * 64 * 4;
        xC[p] = (ccB[p] & 7) << 2;
    }

    float d2[2][8][4];
#pragma unroll
    for (int mt = 0; mt < 2; mt++)
#pragma unroll
        for (int nt = 0; nt < 8; nt++)
#pragma unroll
            for (int q = 0; q < 4; q++) d2[mt][nt][q] = 0.f;

    for (int chunk = 0; chunk < 8; chunk++) {
        int j0 = chunk * JC2;

        __syncthreads();
#pragma unroll
        for (int it = 0; it < 8; it++) {
            int idx = it * 512 + tid;
            int jl = idx >> 5, wc4 = (idx & 31) << 2;
            uint4 v = *(const uint4*)&w1l[(size_t)(j0 + jl) * W + wc4 * 2];
            *(uint4*)&u_b[jl * 128 + (wc4 ^ ((jl & 7) << 2))] = v;
        }
        __syncthreads();

        // ===== GEMM1: D1[128x128] = h2 @ B1, K=256 =====
        float d1[2][4][4];
#pragma unroll
        for (int mt = 0; mt < 2; mt++)
#pragma unroll
            for (int nt = 0; nt < 4; nt++)
#pragma unroll
                for (int q = 0; q < 4; q++) d1[mt][nt][q] = 0.f;

#pragma unroll 4
        for (int ks = 0; ks < 16; ks++) {
            int kwb = ks * 8;
            uint32_t af[2][4];
            ldsm4(af[0], bA0h + (((kwb + koffA) ^ xA0) << 2));
            ldsm4(af[1], bA1h + (((kwb + koffA) ^ xA1) << 2));
            uint32_t bf0[4], bf1[4];
            ldsm4(bf0, bB0 + (((kwb + koffB) ^ xB0) << 2));
            ldsm4(bf1, bB1 + (((kwb + koffB) ^ xB1) << 2));
            mma16(d1[0][0], af[0], bf0);
            mma16(d1[1][0], af[1], bf0);
            mma16(d1[0][1], af[0], bf0 + 2);
            mma16(d1[1][1], af[1], bf0 + 2);
            mma16(d1[0][2], af[0], bf1);
            mma16(d1[1][2], af[1], bf1);
            mma16(d1[0][3], af[0], bf1 + 2);
            mma16(d1[1][3], af[1], bf1 + 2);
        }
        __syncthreads();

        // ---- gelu -> G ; stage B2 ----
#pragma unroll
        for (int mt = 0; mt < 2; mt++) {
#pragma unroll
            for (int nt = 0; nt < 4; nt++) {
                int r0 = wm * 32 + mt * 16 + g;
                int jc = wn * 32 + nt * 8 + 2 * tig;
                int wc = wn * 16 + nt * 4 + tig;
                float x0 = d1[mt][nt][0] + b1l[j0 + jc];
                float x1 = d1[mt][nt][1] + b1l[j0 + jc + 1];
                float x2 = d1[mt][nt][2] + b1l[j0 + jc];
                float x3 = d1[mt][nt][3] + b1l[j0 + jc + 1];
                float g0 = 0.5f * x0 * (1.0f + erff(x0 * 0.7071067811865476f));
                float g1 = 0.5f * x1 * (1.0f + erff(x1 * 0.7071067811865476f));
                float g2v = 0.5f * x2 * (1.0f + erff(x2 * 0.7071067811865476f));
                float g3 = 0.5f * x3 * (1.0f + erff(x3 * 0.7071067811865476f));
                __half2 p0 = __floats2half2_rn(g0, g1);
                __half2 p1 = __floats2half2_rn(g2v, g3);
                u_g[r0 * 64 + (wc ^ ((r0 & 7) << 2))] = *(uint32_t*)&p0;
                int r1 = r0 + 8;
                u_g[r1 * 64 + (wc ^ ((r1 & 7) << 2))] = *(uint32_t*)&p1;
            }
        }
#pragma unroll
        for (int it = 0; it < 8; it++) {
            int idx = it * 512 + tid;
            int cc = idx >> 4, wc4 = (idx & 15) << 2;
            uint4 v = *(const uint4*)&w2l[(size_t)cc * FF + j0 + wc4 * 2];
            *(uint4*)&u_b[cc * 64 + (wc4 ^ ((cc & 7) << 2))] = v;
        }
        __syncthreads();

        // ===== GEMM2 partial: D2[128x256] += G @ B2, K=128 =====
#pragma unroll 2
        for (int ks = 0; ks < 8; ks++) {
            int kwb = ks * 8;
            uint32_t af[2][4];
            ldsm4(af[0], bA0g + (((kwb + koffA) ^ xA0) << 2));
            ldsm4(af[1], bA1g + (((kwb + koffA) ^ xA1) << 2));
#pragma unroll
            for (int p = 0; p < 4; p++) {
                uint32_t bf[4];
                ldsm4(bf, bC[p] + (((kwb + koffB) ^ xC[p]) << 2));
                mma16(d2[0][2 * p],     af[0], bf);
                mma16(d2[1][2 * p],     af[1], bf);
                mma16(d2[0][2 * p + 1], af[0], bf + 2);
                mma16(d2[1][2 * p + 1], af[1], bf + 2);
            }
        }
    }

    // ---- epilogue: x = x_mid + D2 + b2 ----
    const float* b2l = f2b + layer * W;
#pragma unroll
    for (int mt = 0; mt < 2; mt++) {
#pragma unroll
        for (int nt = 0; nt < 8; nt++) {
            int col = wn * 64 + nt * 8 + 2 * tig;
            int ra = wm * 32 + mt * 16 + g;
            float2 xm = *(const float2*)&g_x[xbase + (size_t)ra * W + col];
            float2 o;
            o.x = xm.x + d2[mt][nt][0] + b2l[col];
            o.y = xm.y + d2[mt][nt][1] + b2l[col + 1];
            *(float2*)&g_x[xbase + (size_t)ra * W + col] = o;
            int rb = ra + 8;
            float2 xm2 = *(const float2*)&g_x[xbase + (size_t)rb * W + col];
            o.x = xm2.x + d2[mt][nt][2] + b2l[col];
            o.y = xm2.y + d2[mt][nt][3] + b2l[col + 1];
            *(float2*)&g_x[xbase + (size_t)rb * W + col] = o;
        }
    }
}

// ---------------- K5: final projection ----------------
__global__ void __launch_bounds__(256) proj_kernel(
    const float* __restrict__ pw_, const float* __restrict__ pb, float* __restrict__ out)
{
    __shared__ float xs[16][W];
    size_t t0 = (size_t)blockIdx.x * 16;
    for (int i = threadIdx.x; i < 16 * W; i += 256)
        xs[i >> 8][i & 255] = g_x[t0 * W + i];
    __syncthreads();
    if (threadIdx.x < 64) {
        int t = threadIdx.x >> 2, o = threadIdx.x & 3;
        float acc = pb[o];
#pragma unroll 8
        for (int c = 0; c < W; c++) acc += xs[t][c] * pw_[c * CIN + o];
        out[(t0 + t) * CIN + o] = acc;
    }
}

// ---------------- launch ----------------
extern "C" void kernel_launch(void* const* d_in, const int* in_sizes, int n_in,
                              void* d_out, int out_size)
{
    const float* feat = (const float*)d_in[0];
    const float* coords = (const float*)d_in[1];
    const float* tn   = (const float*)d_in[2];
    const float* ew   = (const float*)d_in[3];
    const float* eb   = (const float*)d_in[4];
    const float* ln1g = (const float*)d_in[5];
    const float* ln1b = (const float*)d_in[6];
    const float* sw   = (const float*)d_in[7];
    const float* sb   = (const float*)d_in[8];
    const float* qkvw = (const float*)d_in[9];
    const float* qkvb = (const float*)d_in[10];
    const float* outw = (const float*)d_in[11];
    const float* outb = (const float*)d_in[12];
    const float* ln2g = (const float*)d_in[13];
    const float* ln2b = (const float*)d_in[14];
    const float* f1w  = (const float*)d_in[15];
    const float* f1b  = (const float*)d_in[16];
    const float* f2w  = (const float*)d_in[17];
    const float* f2b  = (const float*)d_in[18];
    const float* pwp  = (const float*)d_in[19];
    const float* pb   = (const float*)d_in[20];

    static int attr_set = 0;
    if (!attr_set) {
        cudaFuncSetAttribute(ffn_mma_kernel, cudaFuncAttributeMaxDynamicSharedMemorySize, SM_FFN_BYTES);
        cudaFuncSetAttribute(slice_kernel, cudaFuncAttributeMaxDynamicSharedMemorySize, SLICE_SMEM);
        attr_set = 1;
    }

    embed_kernel<<<B * N / 16, 256>>>(feat, coords, tn, ew, eb);
    w1t_kernel<<<L * FF * W / 256, 256>>>(f1w);
    w2t_zero_kernel<<<NB_W2T + NB_Z + 1, 256>>>(f2w);

    for (int l = 0; l < L; l++) {
        slice_kernel<<<B * (N / TOK1), 256, SLICE_SMEM>>>(ln1g, ln1b, sw, sb, l);
        qkv_kernel<<<B * M, 768>>>(qkvw, qkvb, l);
        attn_kernel<<<B * H, 256>>>();
        zp_kernel<<<B * M, 256>>>(outw, outb, l);
        ffn_mma_kernel<<<B * (N / TOKF), 512, SM_FFN_BYTES>>>(ln2g, ln2b, f1b, f2b, l);
    }

    proj_kernel<<<(B * N) / 16, 256>>>(pwp, pb, (float*)d_out);
}